// round 2
// baseline (speedup 1.0000x reference)
#include <cuda_runtime.h>

#define W 8192
#define H 2048
#define NPIX (W * H)

// pitch = (1 - i/H) * (FOV_UP + |FOV_DOWN|) - |FOV_DOWN|
#define FOV_SPAN     0.5235987755982988f   // 30 deg in rad
#define FOV_ABS_DOWN 0.2617993877991494f   // 15 deg in rad
#define TWO_PI       6.283185307179586f
#define PI_F         3.141592653589793f

// Rotation by one column step, theta = 2*pi/8192 (high-precision literals,
// rounded to nearest f32 by the compiler).
#define ROT_C 0.999999705862867f
#define ROT_S 0.000766990318746f

// Quarter-density yaw table: entry g = (cos,sin) of yaw at column 4*g.
// 2048 * 8 B = 16 KB. Pitch table 8 KB. Both stay hot in L1/L2.
static __device__ float2 g_cs_yaw4[W / 4];
static __device__ float  g_sin_pitch[H];

__global__ void fill_tables_kernel() {
    int t = blockIdx.x * blockDim.x + threadIdx.x;
    if (t < W / 4) {
        // yaw at column j = 4t, same f32 formulation as reference
        float yaw = (float)(4 * t) / (float)W * TWO_PI - PI_F;
        float s, c;
        sincosf(yaw, &s, &c);
        g_cs_yaw4[t] = make_float2(c, s);
    }
    if (t < H) {
        float pitch = (1.0f - (float)t / (float)H) * FOV_SPAN - FOV_ABS_DOWN;
        g_sin_pitch[t] = sinf(pitch);
    }
}

// Each thread: 4 consecutive pixels of one row.
//   loads:  4 x float4 image (64 B contiguous/thread) + 1 x float2 yaw (coalesced) + pitch (broadcast)
//   compute: 3 Givens rotations (12 FMA) recover cos/sin for cols j+1..j+3
//   stores: 3 x float4 (48 B contiguous, 16B-aligned)
__global__ void __launch_bounds__(256)
proj_to_pointcloud_kernel(const float4* __restrict__ img, float4* __restrict__ out) {
    int t = blockIdx.x * blockDim.x + threadIdx.x;
    int p = t << 2;              // base pixel index (multiple of 4, same row)
    int i = p >> 13;             // row    (p / 8192)
    int g = t & (W / 4 - 1);     // yaw-group index (column j = 4g)

    // Streaming loads: evict-first so the 256 MB stream doesn't evict the tables.
    float4 p0 = __ldcs(img + p);
    float4 p1 = __ldcs(img + p + 1);
    float4 p2 = __ldcs(img + p + 2);
    float4 p3 = __ldcs(img + p + 3);

    float  sp  = g_sin_pitch[i];
    float2 cs0 = g_cs_yaw4[g];   // fully coalesced: lane t reads entry t

    // Rotate by theta three times: (c,s) -> (c*C - s*S, s*C + c*S)
    float c0 = cs0.x, s0 = cs0.y;
    float c1 = fmaf(c0, ROT_C, -s0 * ROT_S);
    float s1 = fmaf(s0, ROT_C,  c0 * ROT_S);
    float c2 = fmaf(c1, ROT_C, -s1 * ROT_S);
    float s2 = fmaf(s1, ROT_C,  c1 * ROT_S);
    float c3 = fmaf(c2, ROT_C, -s2 * ROT_S);
    float s3 = fmaf(s2, ROT_C,  c2 * ROT_S);

    float d0 = p0.w, d1 = p1.w, d2 = p2.w, d3 = p3.w;

    float x0 =  d0 * c0, y0 = -d0 * s0, z0 = d0 * sp;
    float x1 =  d1 * c1, y1 = -d1 * s1, z1 = d1 * sp;
    float x2 =  d2 * c2, y2 = -d2 * s2, z2 = d2 * sp;
    float x3 =  d3 * c3, y3 = -d3 * s3, z3 = d3 * sp;

    float4 o0 = make_float4(x0, y0, z0, x1);
    float4 o1 = make_float4(y1, z1, x2, y2);
    float4 o2 = make_float4(z2, x3, y3, z3);

    long ob = (long)t * 3;
    __stcs(out + ob,     o0);
    __stcs(out + ob + 1, o1);
    __stcs(out + ob + 2, o2);
}

extern "C" void kernel_launch(void* const* d_in, const int* in_sizes, int n_in,
                              void* d_out, int out_size) {
    const float4* img = (const float4*)d_in[0];
    float4* out = (float4*)d_out;

    // Prologue: fill yaw/pitch tables (tiny).
    fill_tables_kernel<<<(H + 255) / 256, 256>>>();

    // Main streaming kernel: NPIX/4 threads.
    int threads = 256;
    int total_threads = NPIX / 4;            // 4,194,304
    int blocks = total_threads / threads;    // 16,384
    proj_to_pointcloud_kernel<<<blocks, threads>>>(img, out);
}

// round 3
// speedup vs baseline: 1.3868x; 1.3868x over previous
#include <cuda_runtime.h>

#define W 8192
#define H 2048
#define NPIX (W * H)

// pitch = (1 - i/H) * (FOV_UP + |FOV_DOWN|) - |FOV_DOWN|
#define FOV_SPAN     0.5235987755982988f   // 30 deg in rad
#define FOV_ABS_DOWN 0.2617993877991494f   // 15 deg in rad
#define TWO_PI       6.283185307179586f
#define PI_F         3.141592653589793f

// Rotation by one column step, theta = 2*pi/8192.
#define ROT_C 0.999999705862867f
#define ROT_S 0.000766990318746f

// Quarter-density yaw table (16 KB) + pitch table (8 KB): L1/L2 resident.
static __device__ float2 g_cs_yaw4[W / 4];
static __device__ float  g_sin_pitch[H];

__global__ void fill_tables_kernel() {
    int t = blockIdx.x * blockDim.x + threadIdx.x;
    if (t < W / 4) {
        float yaw = (float)(4 * t) / (float)W * TWO_PI - PI_F;
        float s, c;
        sincosf(yaw, &s, &c);
        g_cs_yaw4[t] = make_float2(c, s);
    }
    if (t < H) {
        float pitch = (1.0f - (float)t / (float)H) * FOV_SPAN - FOV_ABS_DOWN;
        g_sin_pitch[t] = sinf(pitch);
    }
}

// Forced 128-bit streaming load. asm volatile so ptxas cannot dead-code
// narrow it to LDG.32 (which quadruples L1 wavefronts for this layout —
// every 32B sector holds 2 depths, so full-width loads are free in DRAM
// terms and 4x cheaper in L1 terms).
__device__ __forceinline__ float ldg128_depth_cs(const float4* a) {
    float x, y, z, w;
    asm volatile("ld.global.cs.v4.f32 {%0,%1,%2,%3}, [%4];"
                 : "=f"(x), "=f"(y), "=f"(z), "=f"(w) : "l"(a));
    return w;
}

// Each thread: 4 consecutive pixels of one row.
//   loads:  4 x forced LDG.128 image (16 wf/warp) + 1 coalesced float2 yaw (2 wf) + pitch
//   compute: 3 Givens rotations recover cos/sin for cols j+1..j+3
//   stores: 3 x STG.128 (12 wf/warp)
__global__ void __launch_bounds__(256)
proj_to_pointcloud_kernel(const float4* __restrict__ img, float4* __restrict__ out) {
    int t = blockIdx.x * blockDim.x + threadIdx.x;
    int p = t << 2;              // base pixel (multiple of 4, same row)
    int i = p >> 13;             // row
    int g = t & (W / 4 - 1);     // yaw-group index (column j = 4g)

    // Front-batch the 4 vector loads for MLP.
    float d0 = ldg128_depth_cs(img + p);
    float d1 = ldg128_depth_cs(img + p + 1);
    float d2 = ldg128_depth_cs(img + p + 2);
    float d3 = ldg128_depth_cs(img + p + 3);

    float  sp  = g_sin_pitch[i];
    float2 cs0 = g_cs_yaw4[g];   // lane t reads entry t: fully coalesced

    // Rotate by theta three times: (c,s) -> (c*C - s*S, s*C + c*S)
    float c0 = cs0.x, s0 = cs0.y;
    float c1 = fmaf(c0, ROT_C, -s0 * ROT_S);
    float s1 = fmaf(s0, ROT_C,  c0 * ROT_S);
    float c2 = fmaf(c1, ROT_C, -s1 * ROT_S);
    float s2 = fmaf(s1, ROT_C,  c1 * ROT_S);
    float c3 = fmaf(c2, ROT_C, -s2 * ROT_S);
    float s3 = fmaf(s2, ROT_C,  c2 * ROT_S);

    float x0 =  d0 * c0, y0 = -d0 * s0, z0 = d0 * sp;
    float x1 =  d1 * c1, y1 = -d1 * s1, z1 = d1 * sp;
    float x2 =  d2 * c2, y2 = -d2 * s2, z2 = d2 * sp;
    float x3 =  d3 * c3, y3 = -d3 * s3, z3 = d3 * sp;

    float4 o0 = make_float4(x0, y0, z0, x1);
    float4 o1 = make_float4(y1, z1, x2, y2);
    float4 o2 = make_float4(z2, x3, y3, z3);

    long ob = (long)t * 3;
    __stcs(out + ob,     o0);
    __stcs(out + ob + 1, o1);
    __stcs(out + ob + 2, o2);
}

extern "C" void kernel_launch(void* const* d_in, const int* in_sizes, int n_in,
                              void* d_out, int out_size) {
    const float4* img = (const float4*)d_in[0];
    float4* out = (float4*)d_out;

    fill_tables_kernel<<<(H + 255) / 256, 256>>>();

    int threads = 256;
    int total_threads = NPIX / 4;            // 4,194,304
    int blocks = total_threads / threads;    // 16,384
    proj_to_pointcloud_kernel<<<blocks, threads>>>(img, out);
}